// round 2
// baseline (speedup 1.0000x reference)
#include <cuda_runtime.h>
#include <math.h>
#include <stdint.h>
#include <stddef.h>

// -------- problem dims --------
#define cB   128
#define cP   196
#define cD   2048
#define cA   512
#define cE   512
#define cH   512
#define cV   10000
#define cT   19
#define cTMAX 20
#define cROWS (cB*cP)        // 25088
#define cKCAT (cE+cD+cH)     // 3072
#define cNG   (4*cH)         // 2048

// -------- device scratch (static; no allocations allowed) --------
__device__ float g_att1[cROWS * cA];          // raw features@enc_w (51.4 MB)
__device__ float g_meanf[cB * cD];
__device__ float g_h[cB * cH];
__device__ float g_c[cB * cH];
__device__ float g_hnew[cB * cH];
__device__ float g_e[cB * cP];
__device__ float g_alpha[cB * cP];
__device__ float g_xin[cB * cKCAT];           // [e_t | awe | h]
__device__ float g_wcat[cKCAT * cNG];         // [w_ih ; w_hh] (25 MB)
__device__ float g_bcat[cNG];
__device__ float g_p_att2[8 * cB * cA];       // split-K partials
__device__ float g_p_gate[4 * cB * cD];
__device__ float g_p_gates[8 * cB * cNG];
__device__ float g_p_cls[cB * cV];
__device__ float g_p_init[8 * cB * cH];

__device__ __forceinline__ float sigf(float x) { return 1.f / (1.f + __expf(-x)); }

// ============================================================================
// Split-K tiled GEMM: P[((s*M)+m)*N + n] = sum_{k in chunk s} A[m,k]*B[k,n]
// A: MxK row-major, B: KxN row-major. grid=(M/64, ceil(N/128), SK), 256 thr.
// BM=64 BN=128 BK=8, per-thread 4x8. M must be a multiple of 64, chunk of 8.
// ============================================================================
__global__ __launch_bounds__(256, 2) void gemm_k(
    const float* __restrict__ A, const float* __restrict__ B,
    float* __restrict__ P, int M, int N, int K)
{
    const int SK = gridDim.z;
    const int kc = K / SK;               // chunk length (mult of 8)
    const int nt = kc >> 3;
    const int k0 = blockIdx.z * kc;
    const int m0 = blockIdx.x * 64;
    const int n0 = blockIdx.y * 128;
    const int tid = threadIdx.x;

    __shared__ __align__(16) float As[8][64];
    __shared__ __align__(16) float Bs[8][128];

    const int ar = tid >> 2;             // 0..63
    const int ac = (tid & 3) << 1;       // 0,2,4,6
    const int br = tid >> 5;             // 0..7
    const int bc = (tid & 31) << 2;      // 0..124
    const int col = n0 + bc;

    const float* Ap = A + (size_t)(m0 + ar) * K + k0 + ac;
    const float* Bp = B + (size_t)(k0 + br) * N + col;
    const bool full4 = (col + 3) < N;

    const int ty = tid >> 4;             // 0..15 -> rows ty*4..+3
    const int tx = tid & 15;             // 0..15 -> cols tx*8..+7

    float acc[4][8];
#pragma unroll
    for (int r = 0; r < 4; r++)
#pragma unroll
        for (int j = 0; j < 8; j++) acc[r][j] = 0.f;

    for (int kt = 0; kt < nt; ++kt) {
        float2 av = *(const float2*)(Ap + kt * 8);
        float b0, b1, b2, b3;
        const float* bp = Bp + (size_t)kt * 8 * N;
        if (full4) { float4 bv = *(const float4*)bp; b0 = bv.x; b1 = bv.y; b2 = bv.z; b3 = bv.w; }
        else {
            b0 = (col     < N) ? bp[0] : 0.f;
            b1 = (col + 1 < N) ? bp[1] : 0.f;
            b2 = (col + 2 < N) ? bp[2] : 0.f;
            b3 = (col + 3 < N) ? bp[3] : 0.f;
        }
        __syncthreads();
        As[ac][ar]     = av.x;
        As[ac + 1][ar] = av.y;
        *(float4*)&Bs[br][bc] = make_float4(b0, b1, b2, b3);
        __syncthreads();
#pragma unroll
        for (int kk = 0; kk < 8; ++kk) {
            float4 a  = *(const float4*)&As[kk][ty * 4];
            float4 v0 = *(const float4*)&Bs[kk][tx * 8];
            float4 v1 = *(const float4*)&Bs[kk][tx * 8 + 4];
            float am[4] = {a.x, a.y, a.z, a.w};
            float bm[8] = {v0.x, v0.y, v0.z, v0.w, v1.x, v1.y, v1.z, v1.w};
#pragma unroll
            for (int r = 0; r < 4; r++)
#pragma unroll
                for (int j = 0; j < 8; j++) acc[r][j] = fmaf(am[r], bm[j], acc[r][j]);
        }
    }

    float* base = P + (size_t)blockIdx.z * M * N;
#pragma unroll
    for (int r = 0; r < 4; r++) {
        int m = m0 + ty * 4 + r;
        int nb = n0 + tx * 8;
        float* prow = base + (size_t)m * N + nb;
#pragma unroll
        for (int j = 0; j < 8; j++)
            if (nb + j < N) prow[j] = acc[r][j];
    }
}

// ============================================================================
// One-time kernels
// ============================================================================
__global__ void meanf_kernel(const float* __restrict__ F) {
    int b = blockIdx.y;
    int d = blockIdx.x * 256 + threadIdx.x;
    const float* f = F + (size_t)b * cP * cD + d;
    float acc = 0.f;
#pragma unroll 4
    for (int p = 0; p < cP; p++) acc += f[(size_t)p * cD];
    g_meanf[b * cD + d] = acc * (1.f / 196.f);
}

__global__ void wcat_kernel(const float* __restrict__ w_ih, const float* __restrict__ w_hh,
                            const float* __restrict__ b_ih, const float* __restrict__ b_hh) {
    int i0 = blockIdx.x * 256 + threadIdx.x;
    if (i0 < cNG) g_bcat[i0] = b_ih[i0] + b_hh[i0];
    int total = cKCAT * cNG;
    int stride = gridDim.x * 256;
    for (int idx = i0; idx < total; idx += stride) {
        int r = idx / cNG;
        g_wcat[idx] = (r < cE + cD) ? w_ih[idx]
                                    : w_hh[(size_t)(r - (cE + cD)) * cNG + (idx % cNG)];
    }
}

__global__ void epi_bias(const float* __restrict__ part, const float* __restrict__ bias,
                         float* __restrict__ dst, int M, int N, int SK) {
    int total = M * N;
    int stride = gridDim.x * blockDim.x;
    for (int idx = blockIdx.x * blockDim.x + threadIdx.x; idx < total; idx += stride) {
        int m = idx / N, n = idx - m * N;
        float v = bias[n];
        for (int s = 0; s < SK; s++) v += part[((size_t)s * M + m) * N + n];
        dst[idx] = v;
    }
}

// ============================================================================
// Per-step kernels
// ============================================================================
// e[b,p] = att_b + sum_a relu(att1raw[b,p,a] + enc_b[a] + att2[b,a]) * att_w[a]
__global__ __launch_bounds__(256) void e_kernel(
    const float* __restrict__ dec_b, const float* __restrict__ enc_b,
    const float* __restrict__ att_w, const float* __restrict__ att_b) {
    int b = blockIdx.x;
    __shared__ float s_base[cA];
    __shared__ float s_w[cA];
    for (int a = threadIdx.x; a < cA; a += 256) {
        float v = dec_b[a] + enc_b[a];
#pragma unroll
        for (int s = 0; s < 8; s++) v += g_p_att2[((size_t)s * cB + b) * cA + a];
        s_base[a] = v;
        s_w[a] = att_w[a];
    }
    __syncthreads();
    int warp = threadIdx.x >> 5, lane = threadIdx.x & 31;
    for (int p = warp; p < cP; p += 8) {
        const float* row = g_att1 + ((size_t)b * cP + p) * cA;
        float acc = 0.f;
#pragma unroll
        for (int i = 0; i < 16; i++) {
            int a = lane + 32 * i;
            float x = row[a] + s_base[a];
            acc = fmaf(fmaxf(x, 0.f), s_w[a], acc);
        }
#pragma unroll
        for (int off = 16; off > 0; off >>= 1)
            acc += __shfl_xor_sync(0xffffffffu, acc, off);
        if (lane == 0) g_e[b * cP + p] = acc + att_b[0];
    }
}

__global__ __launch_bounds__(256) void softmax_alpha(const int* __restrict__ lengths,
                                                     float* __restrict__ out_alpha, int t) {
    int b = blockIdx.x;
    int tid = threadIdx.x;
    __shared__ float red[256];
    float v = (tid < cP) ? g_e[b * cP + tid] : -3.4e38f;
    red[tid] = v;
    __syncthreads();
    for (int off = 128; off > 0; off >>= 1) {
        if (tid < off) red[tid] = fmaxf(red[tid], red[tid + off]);
        __syncthreads();
    }
    float mx = red[0];
    __syncthreads();
    float ex = (tid < cP) ? expf(v - mx) : 0.f;
    red[tid] = ex;
    __syncthreads();
    for (int off = 128; off > 0; off >>= 1) {
        if (tid < off) red[tid] += red[tid + off];
        __syncthreads();
    }
    float s = red[0];
    if (tid < cP) {
        float a = ex / s;
        g_alpha[b * cP + tid] = a;
        float m = (t < lengths[b] - 1) ? 1.f : 0.f;
        out_alpha[((size_t)b * cT + t) * cP + tid] = a * m;
    }
}

__global__ void xinprep(const float* __restrict__ emb, const int* __restrict__ captions, int t) {
    int b = blockIdx.x;
    int cap = captions[b * cTMAX + t];
    const float* er = emb + (size_t)cap * cE;
    for (int i = threadIdx.x; i < cE; i += blockDim.x) {
        g_xin[(size_t)b * cKCAT + i] = er[i];
        g_xin[(size_t)b * cKCAT + cE + cD + i] = g_h[b * cH + i];
    }
}

// awe[b,d] = sigmoid(beta_b[d] + sum_s gate_part) * sum_p alpha[b,p]*features[b,p,d]
__global__ __launch_bounds__(256) void awe_kernel(const float* __restrict__ features,
                                                  const float* __restrict__ beta_b) {
    int b = blockIdx.y;
    int d = blockIdx.x * 256 + threadIdx.x;
    __shared__ float s_al[cP];
    if (threadIdx.x < cP) s_al[threadIdx.x] = g_alpha[b * cP + threadIdx.x];
    __syncthreads();
    float gv = beta_b[d];
#pragma unroll
    for (int s = 0; s < 4; s++) gv += g_p_gate[((size_t)s * cB + b) * cD + d];
    float gate = sigf(gv);
    const float* f = features + (size_t)b * cP * cD + d;
    float acc = 0.f;
#pragma unroll 4
    for (int p = 0; p < cP; p++) acc = fmaf(s_al[p], f[(size_t)p * cD], acc);
    g_xin[(size_t)b * cKCAT + cE + d] = gate * acc;
}

__global__ __launch_bounds__(512) void lstm_kernel(const int* __restrict__ lengths, int t) {
    int b = blockIdx.x;
    int j = threadIdx.x;  // 0..511
    float gi = g_bcat[j], gf = g_bcat[cH + j], gg = g_bcat[2 * cH + j], go = g_bcat[3 * cH + j];
#pragma unroll
    for (int s = 0; s < 8; s++) {
        const float* row = g_p_gates + ((size_t)s * cB + b) * cNG;
        gi += row[j]; gf += row[cH + j]; gg += row[2 * cH + j]; go += row[3 * cH + j];
    }
    float c_old = g_c[b * cH + j];
    float c_new = sigf(gf) * c_old + sigf(gi) * tanhf(gg);
    float h_new = sigf(go) * tanhf(c_new);
    g_hnew[b * cH + j] = h_new;
    bool m = t < lengths[b] - 1;
    if (m) { g_h[b * cH + j] = h_new; g_c[b * cH + j] = c_new; }
}

__global__ void y_epi(const float* __restrict__ cls_b, const int* __restrict__ lengths,
                      float* __restrict__ out_y, int t) {
    int total = cB * cV;
    int stride = gridDim.x * blockDim.x;
    for (int idx = blockIdx.x * blockDim.x + threadIdx.x; idx < total; idx += stride) {
        int b = idx / cV, v = idx - b * cV;
        float m = (t < lengths[b] - 1) ? 1.f : 0.f;
        out_y[((size_t)b * cT + t) * cV + v] = (g_p_cls[idx] + cls_b[v]) * m;
    }
}

// ============================================================================
// host launcher
// ============================================================================
extern "C" void kernel_launch(void* const* d_in, const int* in_sizes, int n_in,
                              void* d_out, int out_size) {
    const float* features = (const float*)d_in[0];
    const int*   captions = (const int*)d_in[1];
    const int*   lengths  = (const int*)d_in[2];
    const float* emb      = (const float*)d_in[3];
    const float* h_fc_w   = (const float*)d_in[4];
    const float* h_fc_b   = (const float*)d_in[5];
    const float* c_fc_w   = (const float*)d_in[6];
    const float* c_fc_b   = (const float*)d_in[7];
    const float* enc_w    = (const float*)d_in[8];
    const float* enc_b    = (const float*)d_in[9];
    const float* dec_w    = (const float*)d_in[10];
    const float* dec_b    = (const float*)d_in[11];
    const float* att_w    = (const float*)d_in[12];
    const float* att_b    = (const float*)d_in[13];
    const float* beta_w   = (const float*)d_in[14];
    const float* beta_b   = (const float*)d_in[15];
    const float* w_ih     = (const float*)d_in[16];
    const float* b_ih     = (const float*)d_in[17];
    const float* w_hh     = (const float*)d_in[18];
    const float* b_hh     = (const float*)d_in[19];
    const float* cls_w    = (const float*)d_in[20];
    const float* cls_b    = (const float*)d_in[21];

    float* out_y = (float*)d_out;                         // (B, T, V)
    float* out_alpha = out_y + (size_t)cB * cT * cV;      // (B, T, P)

    float *att1, *meanf, *h, *c, *hnew, *xin, *wcat, *p_att2, *p_gate, *p_gates, *p_cls, *p_init;
    cudaGetSymbolAddress((void**)&att1,   g_att1);
    cudaGetSymbolAddress((void**)&meanf,  g_meanf);
    cudaGetSymbolAddress((void**)&h,      g_h);
    cudaGetSymbolAddress((void**)&c,      g_c);
    cudaGetSymbolAddress((void**)&hnew,   g_hnew);
    cudaGetSymbolAddress((void**)&xin,    g_xin);
    cudaGetSymbolAddress((void**)&wcat,   g_wcat);
    cudaGetSymbolAddress((void**)&p_att2, g_p_att2);
    cudaGetSymbolAddress((void**)&p_gate, g_p_gate);
    cudaGetSymbolAddress((void**)&p_gates,g_p_gates);
    cudaGetSymbolAddress((void**)&p_cls,  g_p_cls);
    cudaGetSymbolAddress((void**)&p_init, g_p_init);

    // ---- one-time setup ----
    meanf_kernel<<<dim3(cD / 256, cB), 256>>>(features);
    wcat_kernel<<<512, 256>>>(w_ih, w_hh, b_ih, b_hh);

    // h = meanf @ h_fc_w + h_fc_b   (M=128,N=512,K=2048, SK=8)
    gemm_k<<<dim3(2, 4, 8), 256>>>(meanf, h_fc_w, p_init, cB, cH, cD);
    epi_bias<<<256, 256>>>(p_init, h_fc_b, h, cB, cH, 8);
    gemm_k<<<dim3(2, 4, 8), 256>>>(meanf, c_fc_w, p_init, cB, cH, cD);
    epi_bias<<<256, 256>>>(p_init, c_fc_b, c, cB, cH, 8);

    // att1 raw = features @ enc_w   (M=25088,N=512,K=2048)
    gemm_k<<<dim3(cROWS / 64, cA / 128, 1), 256>>>(features, enc_w, att1, cROWS, cA, cD);

    // ---- decode steps ----
    for (int t = 0; t < cT; t++) {
        // att2 partials = h @ dec_w   (128x512x512, SK=8)
        gemm_k<<<dim3(2, 4, 8), 256>>>(h, dec_w, p_att2, cB, cA, cH);
        e_kernel<<<cB, 256>>>(dec_b, enc_b, att_w, att_b);
        softmax_alpha<<<cB, 256>>>(lengths, out_alpha, t);
        xinprep<<<cB, 256>>>(emb, captions, t);
        // gate partials = h @ beta_w  (128x2048x512, SK=4)
        gemm_k<<<dim3(2, 16, 4), 256>>>(h, beta_w, p_gate, cB, cD, cH);
        awe_kernel<<<dim3(cD / 256, cB), 256>>>(features, beta_b);
        // gates partials = xin @ wcat (128x2048x3072, SK=8)
        gemm_k<<<dim3(2, 16, 8), 256>>>(xin, wcat, p_gates, cB, cNG, cKCAT);
        lstm_kernel<<<cB, 512>>>(lengths, t);
        // cls = hnew @ cls_w          (128x10000x512, SK=1)
        gemm_k<<<dim3(2, 79, 1), 256>>>(hnew, cls_w, p_cls, cB, cV, cH);
        y_epi<<<2048, 256>>>(cls_b, lengths, out_y, t);
    }
}

// round 3
// speedup vs baseline: 1.2320x; 1.2320x over previous
#include <cuda_runtime.h>
#include <math.h>
#include <stdint.h>
#include <stddef.h>

// -------- problem dims --------
#define cB   128
#define cP   196
#define cD   2048
#define cA   512
#define cE   512
#define cH   512
#define cV   10000
#define cT   19
#define cTMAX 20
#define cROWS (cB*cP)        // 25088
#define cKCAT (cE+cD+cH)     // 3072
#define cNG   (4*cH)         // 2048
#define cNHW  (cA+cD)        // 2560 (dec_w | beta_w combined)

// -------- device scratch (static; no allocations allowed) --------
__device__ float g_att1[cROWS * cA];          // features@enc_w raw (51.4 MB)
__device__ float g_meanf[cB * cD];
__device__ float g_h[cB * cH];
__device__ float g_c[cB * cH];
__device__ float g_hnew[cB * cH];
__device__ float g_alpha[cB * cP];
__device__ float g_xin[cB * cKCAT];           // [e_t | awe | h]
__device__ float g_wcat[cKCAT * cNG];         // [w_ih ; w_hh]
__device__ float g_bcat[cNG];
__device__ float g_wcomb[cH * cNHW];          // [dec_w | beta_w]
__device__ float g_whc[cD * 1024];            // [h_fc_w | c_fc_w]
__device__ float g_p_hw[8 * cB * cNHW];       // h@wcomb partials (SK=8)
__device__ float g_p_gates[16 * cB * cNG];    // xin@wcat partials (SK=16)
__device__ float g_p_init[4 * cB * 1024];     // meanf@whc partials (SK=4)

__device__ __forceinline__ float sigf(float x) { return 1.f / (1.f + __expf(-x)); }

// packed dual-FMA: d(lo,hi) += a(lo,hi)*b(lo,hi)
#define F2(d,a,b) asm("fma.rn.f32x2 %0, %1, %2, %0;" : "+l"(d) : "l"(a), "l"(b))

// ============================================================================
// gemm2: split-K GEMM, BM=128 BN=128 BK=8, 256 thr, per-thread 8x8, f32x2.
// P[((z*M)+m)*N + n] = sum_{k in chunk z} A[m,k]*B[k,n]
// REQUIRES: M%128==0, N%128==0, (K/SK)%8==0.
// ============================================================================
__global__ __launch_bounds__(256, 2) void gemm2(
    const float* __restrict__ A, const float* __restrict__ B,
    float* __restrict__ P, int M, int N, int K)
{
    const int SK = gridDim.z;
    const int kc = K / SK;
    const int nt = kc >> 3;
    const int k0 = blockIdx.z * kc;
    const int m0 = blockIdx.x * 128;
    const int n0 = blockIdx.y * 128;
    const int tid = threadIdx.x;

    __shared__ __align__(16) float As2[2][8][256];   // A duplicated pairs
    __shared__ __align__(16) float Bs[2][8][128];

    const int arow = tid >> 1;                 // 0..127
    const int akc  = (tid & 1) * 4;            // 0 or 4
    const float* Ap = A + (size_t)(m0 + arow) * K + k0 + akc;
    const int brow = tid >> 5;                 // 0..7
    const int bc4  = (tid & 31) * 4;           // 0..124
    const float* Bp = B + (size_t)(k0 + brow) * N + n0 + bc4;

    const int ty = tid >> 4, tx = tid & 15;

    unsigned long long acc[8][4];
#pragma unroll
    for (int r = 0; r < 8; r++)
#pragma unroll
        for (int p = 0; p < 4; p++) acc[r][p] = 0ull;

    float4 a = *(const float4*)Ap;
    float4 bv = *(const float4*)Bp;
    As2[0][akc + 0][2 * arow] = a.x; As2[0][akc + 0][2 * arow + 1] = a.x;
    As2[0][akc + 1][2 * arow] = a.y; As2[0][akc + 1][2 * arow + 1] = a.y;
    As2[0][akc + 2][2 * arow] = a.z; As2[0][akc + 2][2 * arow + 1] = a.z;
    As2[0][akc + 3][2 * arow] = a.w; As2[0][akc + 3][2 * arow + 1] = a.w;
    *(float4*)&Bs[0][brow][bc4] = bv;
    __syncthreads();

    int cur = 0;
    for (int kt = 0; kt < nt; ++kt) {
        if (kt + 1 < nt) {
            a  = *(const float4*)(Ap + (kt + 1) * 8);
            bv = *(const float4*)(Bp + (size_t)(kt + 1) * 8 * N);
        }
#pragma unroll
        for (int kk = 0; kk < 8; ++kk) {
            const ulonglong2* av = (const ulonglong2*)&As2[cur][kk][ty * 16];
            const ulonglong2* bb = (const ulonglong2*)&Bs[cur][kk][tx * 8];
            ulonglong2 A0 = av[0], A1 = av[1], A2 = av[2], A3 = av[3];
            ulonglong2 B0 = bb[0], B1 = bb[1];
            F2(acc[0][0], A0.x, B0.x); F2(acc[0][1], A0.x, B0.y); F2(acc[0][2], A0.x, B1.x); F2(acc[0][3], A0.x, B1.y);
            F2(acc[1][0], A0.y, B0.x); F2(acc[1][1], A0.y, B0.y); F2(acc[1][2], A0.y, B1.x); F2(acc[1][3], A0.y, B1.y);
            F2(acc[2][0], A1.x, B0.x); F2(acc[2][1], A1.x, B0.y); F2(acc[2][2], A1.x, B1.x); F2(acc[2][3], A1.x, B1.y);
            F2(acc[3][0], A1.y, B0.x); F2(acc[3][1], A1.y, B0.y); F2(acc[3][2], A1.y, B1.x); F2(acc[3][3], A1.y, B1.y);
            F2(acc[4][0], A2.x, B0.x); F2(acc[4][1], A2.x, B0.y); F2(acc[4][2], A2.x, B1.x); F2(acc[4][3], A2.x, B1.y);
            F2(acc[5][0], A2.y, B0.x); F2(acc[5][1], A2.y, B0.y); F2(acc[5][2], A2.y, B1.x); F2(acc[5][3], A2.y, B1.y);
            F2(acc[6][0], A3.x, B0.x); F2(acc[6][1], A3.x, B0.y); F2(acc[6][2], A3.x, B1.x); F2(acc[6][3], A3.x, B1.y);
            F2(acc[7][0], A3.y, B0.x); F2(acc[7][1], A3.y, B0.y); F2(acc[7][2], A3.y, B1.x); F2(acc[7][3], A3.y, B1.y);
        }
        if (kt + 1 < nt) {
            int nb = cur ^ 1;
            As2[nb][akc + 0][2 * arow] = a.x; As2[nb][akc + 0][2 * arow + 1] = a.x;
            As2[nb][akc + 1][2 * arow] = a.y; As2[nb][akc + 1][2 * arow + 1] = a.y;
            As2[nb][akc + 2][2 * arow] = a.z; As2[nb][akc + 2][2 * arow + 1] = a.z;
            As2[nb][akc + 3][2 * arow] = a.w; As2[nb][akc + 3][2 * arow + 1] = a.w;
            *(float4*)&Bs[nb][brow][bc4] = bv;
            __syncthreads();
            cur = nb;
        }
    }

#pragma unroll
    for (int r = 0; r < 8; r++) {
        unsigned long long* prow = (unsigned long long*)
            (P + ((size_t)blockIdx.z * M + m0 + ty * 8 + r) * N + n0 + tx * 8);
        prow[0] = acc[r][0]; prow[1] = acc[r][1];
        prow[2] = acc[r][2]; prow[3] = acc[r][3];
    }
}

// ============================================================================
// gemm_cls: BM=128 BN=64 BK=8, SK=1, fused (bias + mask) epilogue -> out_y.
// A = hnew (128 x 512), B = cls_w (512 x 10000). grid (1, 157).
// ============================================================================
__global__ __launch_bounds__(256, 2) void gemm_cls(
    const float* __restrict__ A, const float* __restrict__ B,
    const float* __restrict__ cls_b, const int* __restrict__ lengths,
    float* __restrict__ out_y, int t)
{
    const int N = cV, K = cH;
    const int nt = K >> 3;                     // 64
    const int n0 = blockIdx.y * 64;
    const int tid = threadIdx.x;

    __shared__ __align__(16) float As2[2][8][256];
    __shared__ __align__(16) float Bs[2][8][64];

    const int arow = tid >> 1;
    const int akc  = (tid & 1) * 4;
    const float* Ap = A + (size_t)arow * K + akc;
    const int brow = tid >> 5;                 // 0..7
    const int bcc  = (tid & 31) * 2;           // 0..62
    const int bcol = n0 + bcc;

    const int ty = tid >> 4, tx = tid & 15;

    unsigned long long acc[8][2];
#pragma unroll
    for (int r = 0; r < 8; r++) { acc[r][0] = 0ull; acc[r][1] = 0ull; }

    float4 a = *(const float4*)Ap;
    float b0 = (bcol     < N) ? B[(size_t)brow * N + bcol]     : 0.f;
    float b1 = (bcol + 1 < N) ? B[(size_t)brow * N + bcol + 1] : 0.f;
    As2[0][akc + 0][2 * arow] = a.x; As2[0][akc + 0][2 * arow + 1] = a.x;
    As2[0][akc + 1][2 * arow] = a.y; As2[0][akc + 1][2 * arow + 1] = a.y;
    As2[0][akc + 2][2 * arow] = a.z; As2[0][akc + 2][2 * arow + 1] = a.z;
    As2[0][akc + 3][2 * arow] = a.w; As2[0][akc + 3][2 * arow + 1] = a.w;
    *(float2*)&Bs[0][brow][bcc] = make_float2(b0, b1);
    __syncthreads();

    int cur = 0;
    for (int kt = 0; kt < nt; ++kt) {
        if (kt + 1 < nt) {
            a = *(const float4*)(Ap + (kt + 1) * 8);
            const float* bp = B + (size_t)((kt + 1) * 8 + brow) * N + bcol;
            b0 = (bcol     < N) ? bp[0] : 0.f;
            b1 = (bcol + 1 < N) ? bp[1] : 0.f;
        }
#pragma unroll
        for (int kk = 0; kk < 8; ++kk) {
            const ulonglong2* av = (const ulonglong2*)&As2[cur][kk][ty * 16];
            ulonglong2 A0 = av[0], A1 = av[1], A2 = av[2], A3 = av[3];
            unsigned long long B0 = *(const unsigned long long*)&Bs[cur][kk][tx * 4];
            unsigned long long B1 = *(const unsigned long long*)&Bs[cur][kk][tx * 4 + 2];
            F2(acc[0][0], A0.x, B0); F2(acc[0][1], A0.x, B1);
            F2(acc[1][0], A0.y, B0); F2(acc[1][1], A0.y, B1);
            F2(acc[2][0], A1.x, B0); F2(acc[2][1], A1.x, B1);
            F2(acc[3][0], A1.y, B0); F2(acc[3][1], A1.y, B1);
            F2(acc[4][0], A2.x, B0); F2(acc[4][1], A2.x, B1);
            F2(acc[5][0], A2.y, B0); F2(acc[5][1], A2.y, B1);
            F2(acc[6][0], A3.x, B0); F2(acc[6][1], A3.x, B1);
            F2(acc[7][0], A3.y, B0); F2(acc[7][1], A3.y, B1);
        }
        if (kt + 1 < nt) {
            int nb = cur ^ 1;
            As2[nb][akc + 0][2 * arow] = a.x; As2[nb][akc + 0][2 * arow + 1] = a.x;
            As2[nb][akc + 1][2 * arow] = a.y; As2[nb][akc + 1][2 * arow + 1] = a.y;
            As2[nb][akc + 2][2 * arow] = a.z; As2[nb][akc + 2][2 * arow + 1] = a.z;
            As2[nb][akc + 3][2 * arow] = a.w; As2[nb][akc + 3][2 * arow + 1] = a.w;
            *(float2*)&Bs[nb][brow][bcc] = make_float2(b0, b1);
            __syncthreads();
            cur = nb;
        }
    }

#pragma unroll
    for (int r = 0; r < 8; r++) {
        int b = ty * 8 + r;
        float mask = (t < lengths[b] - 1) ? 1.f : 0.f;
        float* yrow = out_y + ((size_t)b * cT + t) * cV;
#pragma unroll
        for (int p = 0; p < 2; p++) {
            int col = n0 + tx * 4 + 2 * p;
            unsigned long long v = acc[r][p];
            float lo = __uint_as_float((unsigned)(v & 0xffffffffu));
            float hi = __uint_as_float((unsigned)(v >> 32));
            if (col     < cV) yrow[col]     = (lo + cls_b[col])     * mask;
            if (col + 1 < cV) yrow[col + 1] = (hi + cls_b[col + 1]) * mask;
        }
    }
}

// ============================================================================
// one-time kernels
// ============================================================================
__global__ void meanf_kernel(const float* __restrict__ F) {
    int b = blockIdx.y;
    int d = blockIdx.x * 256 + threadIdx.x;
    const float* f = F + (size_t)b * cP * cD + d;
    float acc = 0.f;
#pragma unroll 4
    for (int p = 0; p < cP; p++) acc += f[(size_t)p * cD];
    g_meanf[b * cD + d] = acc * (1.f / 196.f);
}

__global__ void prep_weights(const float* __restrict__ dec_w, const float* __restrict__ beta_w,
                             const float* __restrict__ h_fc_w, const float* __restrict__ c_fc_w,
                             const float* __restrict__ w_ih, const float* __restrict__ w_hh,
                             const float* __restrict__ b_ih, const float* __restrict__ b_hh) {
    int stride = gridDim.x * blockDim.x;
    int base = blockIdx.x * blockDim.x + threadIdx.x;
    for (int idx = base; idx < cH * cNHW; idx += stride) {
        int k = idx / cNHW, n = idx - k * cNHW;
        g_wcomb[idx] = (n < cA) ? dec_w[k * cA + n] : beta_w[(size_t)k * cD + n - cA];
    }
    for (int idx = base; idx < cD * 1024; idx += stride) {
        int k = idx >> 10, n = idx & 1023;
        g_whc[idx] = (n < cH) ? h_fc_w[k * cH + n] : c_fc_w[k * cH + n - cH];
    }
    for (int idx = base; idx < cKCAT * cNG; idx += stride) {
        int r = idx >> 11;
        g_wcat[idx] = (r < cE + cD) ? w_ih[idx] : w_hh[idx - (cE + cD) * cNG];
    }
    for (int idx = base; idx < cNG; idx += stride)
        g_bcat[idx] = b_ih[idx] + b_hh[idx];
}

__global__ void init_hc(const float* __restrict__ h_fc_b, const float* __restrict__ c_fc_b) {
    int idx = blockIdx.x * 256 + threadIdx.x;   // 128*1024
    int b = idx >> 10, n = idx & 1023;
    float v = 0.f;
#pragma unroll
    for (int s = 0; s < 4; s++) v += g_p_init[((s * cB + b) << 10) + n];
    if (n < cH) g_h[b * cH + n] = v + h_fc_b[n];
    else        g_c[b * cH + n - cH] = v + c_fc_b[n - cH];
}

// ============================================================================
// per-step kernels
// ============================================================================
// Per b: reduce att2 partials; e[p]; softmax -> alpha (+masked output);
// then assemble xin[e_t | ... | h].
__global__ __launch_bounds__(256) void e_softmax_xin(
    const float* __restrict__ dec_b, const float* __restrict__ enc_b,
    const float* __restrict__ att_w, const float* __restrict__ att_b,
    const float* __restrict__ emb, const int* __restrict__ captions,
    const int* __restrict__ lengths, float* __restrict__ out_alpha, int t)
{
    int b = blockIdx.x;
    __shared__ float s_base[cA];
    __shared__ float s_w[cA];
    __shared__ float s_e[cP];
    __shared__ float red[256];
    int tid = threadIdx.x;

    for (int a = tid; a < cA; a += 256) {
        float v = dec_b[a] + enc_b[a];
#pragma unroll
        for (int s = 0; s < 8; s++) v += g_p_hw[((size_t)s * cB + b) * cNHW + a];
        s_base[a] = v;
        s_w[a] = att_w[a];
    }
    __syncthreads();

    int warp = tid >> 5, lane = tid & 31;
    float attb = att_b[0];
    for (int p = warp; p < cP; p += 8) {
        const float* row = g_att1 + ((size_t)b * cP + p) * cA;
        float acc = 0.f;
#pragma unroll
        for (int i = 0; i < 16; i++) {
            int a = lane + 32 * i;
            float x = row[a] + s_base[a];
            acc = fmaf(fmaxf(x, 0.f), s_w[a], acc);
        }
#pragma unroll
        for (int off = 16; off > 0; off >>= 1)
            acc += __shfl_xor_sync(0xffffffffu, acc, off);
        if (lane == 0) s_e[p] = acc + attb;
    }
    __syncthreads();

    float v = (tid < cP) ? s_e[tid] : -3.4e38f;
    red[tid] = v;
    __syncthreads();
    for (int off = 128; off > 0; off >>= 1) {
        if (tid < off) red[tid] = fmaxf(red[tid], red[tid + off]);
        __syncthreads();
    }
    float mx = red[0];
    __syncthreads();
    float ex = (tid < cP) ? expf(v - mx) : 0.f;
    red[tid] = ex;
    __syncthreads();
    for (int off = 128; off > 0; off >>= 1) {
        if (tid < off) red[tid] += red[tid + off];
        __syncthreads();
    }
    float s = red[0];
    if (tid < cP) {
        float al = ex / s;
        g_alpha[b * cP + tid] = al;
        float m = (t < lengths[b] - 1) ? 1.f : 0.f;
        out_alpha[((size_t)b * cT + t) * cP + tid] = al * m;
    }

    int cap = captions[b * cTMAX + t];
    const float* er = emb + (size_t)cap * cE;
    for (int i = tid; i < cE; i += 256) {
        g_xin[(size_t)b * cKCAT + i] = er[i];
        g_xin[(size_t)b * cKCAT + cE + cD + i] = g_h[b * cH + i];
    }
}

// xin[awe part] = sigmoid(beta_b + sum gate partials) * (alpha @ features)
__global__ __launch_bounds__(256) void awe_kernel(const float* __restrict__ features,
                                                  const float* __restrict__ beta_b) {
    int b = blockIdx.y;
    int d = blockIdx.x * 256 + threadIdx.x;
    __shared__ float s_al[cP];
    if (threadIdx.x < cP) s_al[threadIdx.x] = g_alpha[b * cP + threadIdx.x];
    __syncthreads();
    float gv = beta_b[d];
#pragma unroll
    for (int s = 0; s < 8; s++) gv += g_p_hw[((size_t)s * cB + b) * cNHW + cA + d];
    float gate = sigf(gv);
    const float* f = features + (size_t)b * cP * cD + d;
    float acc = 0.f;
#pragma unroll 4
    for (int p = 0; p < cP; p++) acc = fmaf(s_al[p], f[(size_t)p * cD], acc);
    g_xin[(size_t)b * cKCAT + cE + d] = gate * acc;
}

__global__ __launch_bounds__(512) void lstm_kernel(const int* __restrict__ lengths, int t) {
    int b = blockIdx.x;
    int j = threadIdx.x;
    float gi = g_bcat[j], gf = g_bcat[cH + j], gg = g_bcat[2 * cH + j], go = g_bcat[3 * cH + j];
#pragma unroll
    for (int s = 0; s < 16; s++) {
        const float* row = g_p_gates + ((size_t)s * cB + b) * cNG;
        gi += row[j]; gf += row[cH + j]; gg += row[2 * cH + j]; go += row[3 * cH + j];
    }
    float c_old = g_c[b * cH + j];
    float c_new = sigf(gf) * c_old + sigf(gi) * tanhf(gg);
    float h_new = sigf(go) * tanhf(c_new);
    g_hnew[b * cH + j] = h_new;
    if (t < lengths[b] - 1) { g_h[b * cH + j] = h_new; g_c[b * cH + j] = c_new; }
}

// ============================================================================
// host launcher
// ============================================================================
extern "C" void kernel_launch(void* const* d_in, const int* in_sizes, int n_in,
                              void* d_out, int out_size) {
    const float* features = (const float*)d_in[0];
    const int*   captions = (const int*)d_in[1];
    const int*   lengths  = (const int*)d_in[2];
    const float* emb      = (const float*)d_in[3];
    const float* h_fc_w   = (const float*)d_in[4];
    const float* h_fc_b   = (const float*)d_in[5];
    const float* c_fc_w   = (const float*)d_in[6];
    const float* c_fc_b   = (const float*)d_in[7];
    const float* enc_w    = (const float*)d_in[8];
    const float* enc_b    = (const float*)d_in[9];
    const float* dec_w    = (const float*)d_in[10];
    const float* dec_b    = (const float*)d_in[11];
    const float* att_w    = (const float*)d_in[12];
    const float* att_b    = (const float*)d_in[13];
    const float* beta_w   = (const float*)d_in[14];
    const float* beta_b   = (const float*)d_in[15];
    const float* w_ih     = (const float*)d_in[16];
    const float* b_ih     = (const float*)d_in[17];
    const float* w_hh     = (const float*)d_in[18];
    const float* b_hh     = (const float*)d_in[19];
    const float* cls_w    = (const float*)d_in[20];
    const float* cls_b    = (const float*)d_in[21];

    float* out_y = (float*)d_out;                         // (B, T, V)
    float* out_alpha = out_y + (size_t)cB * cT * cV;      // (B, T, P)

    float *att1, *meanf, *h, *hnew, *xin, *wcat, *wcomb, *whc, *p_hw, *p_gates, *p_init;
    cudaGetSymbolAddress((void**)&att1,    g_att1);
    cudaGetSymbolAddress((void**)&meanf,   g_meanf);
    cudaGetSymbolAddress((void**)&h,       g_h);
    cudaGetSymbolAddress((void**)&hnew,    g_hnew);
    cudaGetSymbolAddress((void**)&xin,     g_xin);
    cudaGetSymbolAddress((void**)&wcat,    g_wcat);
    cudaGetSymbolAddress((void**)&wcomb,   g_wcomb);
    cudaGetSymbolAddress((void**)&whc,     g_whc);
    cudaGetSymbolAddress((void**)&p_hw,    g_p_hw);
    cudaGetSymbolAddress((void**)&p_gates, g_p_gates);
    cudaGetSymbolAddress((void**)&p_init,  g_p_init);

    // ---- one-time setup ----
    meanf_kernel<<<dim3(cD / 256, cB), 256>>>(features);
    prep_weights<<<1024, 256>>>(dec_w, beta_w, h_fc_w, c_fc_w, w_ih, w_hh, b_ih, b_hh);

    // [h|c] = meanf @ [h_fc_w|c_fc_w]  (128 x 1024 x 2048, SK=4)
    gemm2<<<dim3(1, 8, 4), 256>>>(meanf, whc, p_init, cB, 1024, cD);
    init_hc<<<512, 256>>>(h_fc_b, c_fc_b);

    // att1 = features @ enc_w  (25088 x 512 x 2048)
    gemm2<<<dim3(cROWS / 128, cA / 128, 1), 256>>>(features, enc_w, att1, cROWS, cA, cD);

    // ---- decode steps ----
    for (int t = 0; t < cT; t++) {
        // [att2|gatepre] = h @ [dec_w|beta_w]  (128 x 2560 x 512, SK=8)
        gemm2<<<dim3(1, cNHW / 128, 8), 256>>>(h, wcomb, p_hw, cB, cNHW, cH);
        e_softmax_xin<<<cB, 256>>>(dec_b, enc_b, att_w, att_b, emb, captions,
                                   lengths, out_alpha, t);
        awe_kernel<<<dim3(cD / 256, cB), 256>>>(features, beta_b);
        // gates = xin @ wcat  (128 x 2048 x 3072, SK=16)
        gemm2<<<dim3(1, cNG / 128, 16), 256>>>(xin, wcat, p_gates, cB, cNG, cKCAT);
        lstm_kernel<<<cB, 512>>>(lengths, t);
        // y = (hnew @ cls_w + cls_b) * mask  (fused epilogue, 157 N-blocks)
        gemm_cls<<<dim3(1, (cV + 63) / 64, 1), 256>>>(hnew, cls_w, cls_b, lengths, out_y, t);
    }
}